// round 4
// baseline (speedup 1.0000x reference)
#include <cuda_runtime.h>

// ---------------- problem constants ----------------
#define B_SZ   4
#define C_IN   32
#define C_OUT  32
#define HW_DIM 256
#define PLANE  (HW_DIM * HW_DIM)   // 65536
#define KTAPS  9

// conv tile: 64 cols x 8 rows, cin processed in four passes of 8
#define TW 64
#define TH 8
#define IW 66
#define IH 10
#define CSPLIT 8
#define NPASS  (C_IN / CSPLIT)   // 4
#define NTHREADS 256

#define SU_U64    (CSPLIT * IH * IW)        // 5280 u64 (duplicated u values)
#define SW_FLOATS (KTAPS * C_IN * C_OUT)    // 9216
#define SS_FLOATS (IH * IW)                 // 660
#define SB_FLOATS 32
#define SP_FLOATS (NTHREADS * 4)            // 1024 partial sums for exp0
// bytes: 5280*8 + (9216+660+32+1024)*4 = 42240 + 43728 = 85968 (~84KB -> 2 blocks/SM)
#define SMEM_BYTES (SU_U64 * 8 + (SW_FLOATS + SS_FLOATS + SB_FLOATS + SP_FLOATS) * 4)

// scratch for log0 scale factors (static __device__: no allocations allowed)
__device__ float g_S[B_SZ * PLANE];

// ---------------- packed f32x2 helpers ----------------
__device__ __forceinline__ unsigned long long packab(float a, float b) {
    unsigned long long r;
    asm("mov.b64 %0, {%1, %2};" : "=l"(r) : "f"(a), "f"(b));
    return r;
}
__device__ __forceinline__ void ffma2(unsigned long long& d,
                                      unsigned long long a,
                                      unsigned long long b) {
    asm("fma.rn.f32x2 %0, %1, %2, %0;" : "+l"(d) : "l"(a), "l"(b));
}
__device__ __forceinline__ void unpack2(unsigned long long v, float& lo, float& hi) {
    asm("mov.b64 {%0, %1}, %2;" : "=f"(lo), "=f"(hi) : "l"(v));
}

// ---------------- kernel 1: log0 scale per pixel ----------------
__global__ void log0_scale_kernel(const float* __restrict__ x) {
    int pid = blockIdx.x * blockDim.x + threadIdx.x;   // 0 .. B*PLANE-1
    int b = pid >> 16;
    int p = pid & (PLANE - 1);
    const float* xb = x + ((size_t)b * C_IN) * PLANE + p;
    float ss = 0.f;
#pragma unroll
    for (int c = 0; c < C_IN; c++) {
        float v = xb[(size_t)c * PLANE];
        ss += v * v;
    }
    float n = fmaxf(sqrtf(ss), 1e-7f);
    float a = fminf(0.1f * n, 1.0f - 1e-6f);
    g_S[pid] = atanhf(a) / (0.1f * n);
}

// ---------------- kernel 2: fused conv + bias + relu + exp0 ----------------
// 256 threads (8 warps): warp w -> cout group g = w>>2 (16 couts),
// row slot = w&3 (2 output rows). Thread: 4 px (2 rows x cols {lane, lane+32})
// x 16 couts. u-tile stored DUPLICATED as (v,v) u64 so the f32x2 multiplicand
// is a single LDS.64 (no pack MOVs). cin streamed in 4 passes of 8 channels.
__global__ __launch_bounds__(NTHREADS, 2)
void pvconv_kernel(const float* __restrict__ x,
                   const float* __restrict__ Wk,
                   const float* __restrict__ bias,
                   float* __restrict__ out) {
    extern __shared__ unsigned long long sm64[];
    unsigned long long* su = sm64;                    // [8][IH][IW] (v,v) pairs
    float* sw    = (float*)(sm64 + SU_U64);           // [k][cin][cout] weights
    float* ssc   = sw + SW_FLOATS;                    // [IH][IW] log0 scales
    float* sb    = ssc + SS_FLOATS;                   // [32] bias
    float* spart = sb + SB_FLOATS;                    // [4][256] exp0 partials

    const int tid = threadIdx.x;
    const int b  = blockIdx.z;
    const int r0 = blockIdx.y * TH;
    const int c0 = blockIdx.x * TW;

    // --- phase 1: weights (transpose [k][o][c] -> [k][c][o]), bias, scale tile ---
    for (int idx = tid; idx < SW_FLOATS; idx += NTHREADS) {
        int k = idx >> 10;
        int rem = idx & 1023;
        int c = rem >> 5;
        int o = rem & 31;
        sw[idx] = Wk[(k << 10) + (o << 5) + c];
    }
    if (tid < 32) sb[tid] = bias[tid];
    {
        const float* Sb = g_S + ((size_t)b << 16);
        for (int idx = tid; idx < SS_FLOATS; idx += NTHREADS) {
            int rr = idx / IW;
            int cc = idx - rr * IW;
            int gh = r0 - 1 + rr, gw = c0 - 1 + cc;
            float v = 0.f;
            if ((unsigned)gh < (unsigned)HW_DIM && (unsigned)gw < (unsigned)HW_DIM)
                v = Sb[(gh << 8) + gw];
            ssc[idx] = v;
        }
    }

    const int lane = tid & 31;
    const int warp = tid >> 5;
    const int g    = warp >> 2;        // cout group: 0 -> [0,16), 1 -> [16,32)
    const int slot = warp & 3;
    const int lr0  = slot << 1;        // this warp-slot's 2 output rows

    unsigned long long acc[4][8];
#pragma unroll
    for (int p = 0; p < 4; p++)
#pragma unroll
        for (int t = 0; t < 8; t++) acc[p][t] = 0ull;

    const float* xb = x + (((size_t)b * C_IN) << 16);

#pragma unroll 1
    for (int pass = 0; pass < NPASS; pass++) {
        __syncthreads();   // previous compute done (or phase-1 done)
        // --- load scaled, duplicated input tile for this cin pass ---
        for (int idx = tid; idx < SU_U64; idx += NTHREADS) {
            int cin = idx / (IH * IW);
            int rem = idx - cin * (IH * IW);
            int rr = rem / IW;
            int cc = rem - rr * IW;
            int gh = r0 - 1 + rr, gw = c0 - 1 + cc;
            float v = 0.f;
            if ((unsigned)gh < (unsigned)HW_DIM && (unsigned)gw < (unsigned)HW_DIM)
                v = xb[((size_t)(pass * CSPLIT + cin) << 16) + (gh << 8) + gw] * ssc[rem];
            su[idx] = packab(v, v);
        }
        __syncthreads();

        // --- compute this pass ---
#pragma unroll 1
        for (int k = 0; k < KTAPS; k++) {
            const int ki = k / 3;
            const int kj = k - ki * 3;
            const unsigned long long* ub = su + (lr0 + ki) * IW + lane + kj;
            const float* wp = sw + (k << 10) + (pass << 8) + (g << 4);

#pragma unroll
            for (int c = 0; c < CSPLIT; c++) {
                const unsigned long long* up = ub + c * (IH * IW);
                unsigned long long pa0 = up[0];
                unsigned long long pa1 = up[32];
                unsigned long long pa2 = up[IW];
                unsigned long long pa3 = up[IW + 32];
                const ulonglong2* wv = (const ulonglong2*)(wp + (c << 5));
                ulonglong2 w0 = wv[0];
                ulonglong2 w1 = wv[1];
                ulonglong2 w2 = wv[2];
                ulonglong2 w3 = wv[3];
                ffma2(acc[0][0], pa0, w0.x); ffma2(acc[0][1], pa0, w0.y);
                ffma2(acc[1][0], pa1, w0.x); ffma2(acc[1][1], pa1, w0.y);
                ffma2(acc[2][0], pa2, w0.x); ffma2(acc[2][1], pa2, w0.y);
                ffma2(acc[3][0], pa3, w0.x); ffma2(acc[3][1], pa3, w0.y);
                ffma2(acc[0][2], pa0, w1.x); ffma2(acc[0][3], pa0, w1.y);
                ffma2(acc[1][2], pa1, w1.x); ffma2(acc[1][3], pa1, w1.y);
                ffma2(acc[2][2], pa2, w1.x); ffma2(acc[2][3], pa2, w1.y);
                ffma2(acc[3][2], pa3, w1.x); ffma2(acc[3][3], pa3, w1.y);
                ffma2(acc[0][4], pa0, w2.x); ffma2(acc[0][5], pa0, w2.y);
                ffma2(acc[1][4], pa1, w2.x); ffma2(acc[1][5], pa1, w2.y);
                ffma2(acc[2][4], pa2, w2.x); ffma2(acc[2][5], pa2, w2.y);
                ffma2(acc[3][4], pa3, w2.x); ffma2(acc[3][5], pa3, w2.y);
                ffma2(acc[0][6], pa0, w3.x); ffma2(acc[0][7], pa0, w3.y);
                ffma2(acc[1][6], pa1, w3.x); ffma2(acc[1][7], pa1, w3.y);
                ffma2(acc[2][6], pa2, w3.x); ffma2(acc[2][7], pa2, w3.y);
                ffma2(acc[3][6], pa3, w3.x); ffma2(acc[3][7], pa3, w3.y);
            }
        }
    }

    // --- bias + relu, partial ||.||^2 per cout-half ---
#pragma unroll
    for (int p = 0; p < 4; p++) {
        float s = 0.f;
#pragma unroll
        for (int t = 0; t < 8; t++) {
            float lo, hi;
            unpack2(acc[p][t], lo, hi);
            lo = fmaxf(lo + sb[(g << 4) + 2 * t], 0.f);
            hi = fmaxf(hi + sb[(g << 4) + 2 * t + 1], 0.f);
            s += lo * lo + hi * hi;
            acc[p][t] = packab(lo, hi);
        }
        spart[(p << 8) + tid] = s;
    }
    __syncthreads();

    // --- combine halves, exp0 scale, planar coalesced stores ---
    const int gh_base = r0 + lr0;
    float* outb = out + (((size_t)(b * C_OUT + g * 16)) << 16);
#pragma unroll
    for (int p = 0; p < 4; p++) {
        float ssum = spart[(p << 8) + tid] + spart[(p << 8) + (tid ^ 128)];
        float n = fmaxf(sqrtf(ssum), 1e-7f);
        float f = tanhf(0.1f * n) / (0.1f * n);
        const int gh = gh_base + (p >> 1);
        const int gw = c0 + lane + ((p & 1) << 5);
        float* ob = outb + (gh << 8) + gw;
#pragma unroll
        for (int t = 0; t < 8; t++) {
            float lo, hi;
            unpack2(acc[p][t], lo, hi);
            ob[(size_t)(2 * t) << 16]     = f * lo;
            ob[(size_t)(2 * t + 1) << 16] = f * hi;
        }
    }
}

// ---------------- launch ----------------
extern "C" void kernel_launch(void* const* d_in, const int* in_sizes, int n_in,
                              void* d_out, int out_size) {
    const float* x    = (const float*)d_in[0];
    const float* Wk   = (const float*)d_in[1];
    const float* bias = (const float*)d_in[2];
    float* out = (float*)d_out;

    cudaFuncSetAttribute(pvconv_kernel,
                         cudaFuncAttributeMaxDynamicSharedMemorySize, SMEM_BYTES);

    // kernel 1: per-pixel log0 scale
    log0_scale_kernel<<<(B_SZ * PLANE) / 256, 256>>>(x);

    // kernel 2: fused conv + bias + relu + exp0
    dim3 grid(HW_DIM / TW, HW_DIM / TH, B_SZ);   // (4, 32, 4) = 512 blocks
    pvconv_kernel<<<grid, NTHREADS, SMEM_BYTES>>>(x, Wk, bias, out);
}

// round 5
// speedup vs baseline: 1.8189x; 1.8189x over previous
#include <cuda_runtime.h>

// ---------------- problem constants ----------------
#define B_SZ   4
#define C_IN   32
#define C_OUT  32
#define HW_DIM 256
#define PLANE  (HW_DIM * HW_DIM)   // 65536
#define KTAPS  9

// conv tile: 64 cols x 8 rows per block, 256 threads = 8 warps (1 row/warp)
#define TW 64
#define TH 8
#define IW 66
#define IH 10
#define NTHREADS 256

#define CIN_STRIDE 664                    // 660 padded to 664 (bank-partition for cin%4)
#define SU_FLOATS (C_IN * CIN_STRIDE)     // 21248
#define SWF_FLOATS (36 * 4 * 64)          // 9216: [kstep][n8][lane][reg] B fragments
#define SS_FLOATS (IH * IW)               // 660
#define SB_FLOATS 32
#define SMEM_FLOATS (SU_FLOATS + SWF_FLOATS + SS_FLOATS + SB_FLOATS)
#define SMEM_BYTES  (SMEM_FLOATS * 4)     // ~124.6 KB -> 1 block/SM

// scratch for log0 scale factors (static __device__: no allocations allowed)
__device__ float g_S[B_SZ * PLANE];

// ---------------- helpers ----------------
__device__ __forceinline__ unsigned to_tf32(float x) {
    unsigned r;
    asm("cvt.rna.tf32.f32 %0, %1;" : "=r"(r) : "f"(x));
    return r;
}

__device__ __forceinline__ void mma_tf32(float* c,
                                         unsigned a0, unsigned a1,
                                         unsigned a2, unsigned a3,
                                         unsigned b0, unsigned b1) {
    asm("mma.sync.aligned.m16n8k8.row.col.f32.tf32.tf32.f32 "
        "{%0,%1,%2,%3},{%4,%5,%6,%7},{%8,%9},{%0,%1,%2,%3};"
        : "+f"(c[0]), "+f"(c[1]), "+f"(c[2]), "+f"(c[3])
        : "r"(a0), "r"(a1), "r"(a2), "r"(a3), "r"(b0), "r"(b1));
}

// ---------------- kernel 1: log0 scale per pixel ----------------
__global__ void log0_scale_kernel(const float* __restrict__ x) {
    int pid = blockIdx.x * blockDim.x + threadIdx.x;   // 0 .. B*PLANE-1
    int b = pid >> 16;
    int p = pid & (PLANE - 1);
    const float* xb = x + ((size_t)b * C_IN) * PLANE + p;
    float ss = 0.f;
#pragma unroll
    for (int c = 0; c < C_IN; c++) {
        float v = xb[(size_t)c * PLANE];
        ss += v * v;
    }
    float n = fmaxf(sqrtf(ss), 1e-7f);
    float a = fminf(0.1f * n, 1.0f - 1e-6f);
    g_S[pid] = atanhf(a) / (0.1f * n);
}

// ---------------- kernel 2: tf32 mma implicit-GEMM conv + bias + relu + exp0 ----
// Implicit GEMM: out[px, cout] = sum_{tap,cin} u[shift(px,tap), cin] * W[tap,cin,cout]
// Warp = 1 output row (64 px = 4 x m16). K loop: 9 taps x 4 cin-chunks of 8.
// A fragments gathered directly from the u smem tile (tap shift = pointer offset).
// B fragments pre-swizzled into fragment order at stage time (conflict-free LDS.64).
__global__ __launch_bounds__(NTHREADS, 1)
void pvconv_kernel(const float* __restrict__ x,
                   const float* __restrict__ Wk,
                   const float* __restrict__ bias,
                   float* __restrict__ out) {
    extern __shared__ float sm[];
    float* su  = sm;                       // [32][CIN_STRIDE] tf32 u tile (rows*66+col)
    float* swf = su + SU_FLOATS;           // B fragments [ks][n8][lane][2]
    float* ssc = swf + SWF_FLOATS;         // [IH][IW] log0 scales
    float* sb  = ssc + SS_FLOATS;          // [32] bias

    const int tid = threadIdx.x;
    const int b  = blockIdx.z;
    const int r0 = blockIdx.y * TH;
    const int c0 = blockIdx.x * TW;
    const int lane = tid & 31;
    const int warp = tid >> 5;             // = output row within tile (0..7)

    // --- stage B fragments (tf32), bias, scale tile ---
    for (int fidx = tid; fidx < SWF_FLOATS; fidx += NTHREADS) {
        int reg  = fidx & 1;
        int pair = fidx >> 1;
        int ls   = pair & 31;
        int n8ks = pair >> 5;
        int n8   = n8ks & 3;
        int ks   = n8ks >> 2;
        int tap  = ks >> 2;
        int cc4  = ks & 3;
        int cin  = cc4 * 8 + (ls & 3) + 4 * reg;   // B row (k)
        int cout = n8 * 8 + (ls >> 2);             // B col (n)
        float v = Wk[tap * 1024 + cout * 32 + cin];
        swf[fidx] = __uint_as_float(to_tf32(v));
    }
    if (tid < 32) sb[tid] = bias[tid];
    {
        const float* Sb = g_S + ((size_t)b << 16);
        for (int idx = tid; idx < SS_FLOATS; idx += NTHREADS) {
            int rr = idx / IW;
            int cc = idx - rr * IW;
            int gh = r0 - 1 + rr, gw = c0 - 1 + cc;
            float v = 0.f;
            if ((unsigned)gh < (unsigned)HW_DIM && (unsigned)gw < (unsigned)HW_DIM)
                v = Sb[(gh << 8) + gw];
            ssc[idx] = v;
        }
    }
    __syncthreads();

    // --- stage scaled u tile as tf32 ---
    {
        const float* xb = x + (((size_t)b * C_IN) << 16);
        for (int idx = tid; idx < C_IN * (IH * IW); idx += NTHREADS) {
            int cin = idx / (IH * IW);
            int rem = idx - cin * (IH * IW);
            int rr = rem / IW;
            int cc = rem - rr * IW;
            int gh = r0 - 1 + rr, gw = c0 - 1 + cc;
            float v = 0.f;
            if ((unsigned)gh < (unsigned)HW_DIM && (unsigned)gw < (unsigned)HW_DIM)
                v = xb[((size_t)cin << 16) + (gh << 8) + gw] * ssc[rem];
            su[cin * CIN_STRIDE + rem] = __uint_as_float(to_tf32(v));
        }
    }
    __syncthreads();

    // --- main loop: 9 taps x 4 cin-chunks, 16 mma per k-step ---
    float acc[4][4][4];                    // [g16][n8][reg]
#pragma unroll
    for (int g = 0; g < 4; g++)
#pragma unroll
        for (int n = 0; n < 4; n++)
#pragma unroll
            for (int r = 0; r < 4; r++) acc[g][n][r] = 0.f;

    const int q = lane >> 2;               // 0..7: pixel-col-within-m16 / B cout row
    const int t = lane & 3;                // 0..3: cin-within-chunk / cout pair

#pragma unroll 1
    for (int tap = 0; tap < KTAPS; tap++) {
        const int ki = tap / 3;
        const int kj = tap - ki * 3;
        const float* urow = su + (warp + ki) * IW + q + kj;
#pragma unroll
        for (int cc4 = 0; cc4 < 4; cc4++) {
            const float* ap = urow + (cc4 * 8 + t) * CIN_STRIDE;
            unsigned a[4][4];
#pragma unroll
            for (int g = 0; g < 4; g++) {
                a[g][0] = __float_as_uint(ap[g * 16]);
                a[g][1] = __float_as_uint(ap[g * 16 + 8]);
                a[g][2] = __float_as_uint(ap[g * 16 + 4 * CIN_STRIDE]);
                a[g][3] = __float_as_uint(ap[g * 16 + 8 + 4 * CIN_STRIDE]);
            }
            const float2* bbase =
                (const float2*)swf + (size_t)(tap * 4 + cc4) * 128 + lane;
#pragma unroll
            for (int n8 = 0; n8 < 4; n8++) {
                float2 bb = bbase[n8 * 32];
                unsigned b0 = __float_as_uint(bb.x);
                unsigned b1 = __float_as_uint(bb.y);
#pragma unroll
                for (int g = 0; g < 4; g++)
                    mma_tf32(acc[g][n8], a[g][0], a[g][1], a[g][2], a[g][3], b0, b1);
            }
        }
    }

    __syncthreads();    // everyone done reading su -> safe to reuse as vout

    // --- epilogue: bias + relu + exp0 (4-lane butterfly for the cout norm) ---
    // thread's pixels: cols g*16+q and g*16+q+8 (row = warp); couts n8*8+2t(+1)
    float* vout = su + warp * (C_OUT * 65);   // [cout][65] per-warp staging
#pragma unroll
    for (int g = 0; g < 4; g++) {
        float s0 = 0.f, s1 = 0.f;
#pragma unroll
        for (int n8 = 0; n8 < 4; n8++) {
            float2 bb = ((const float2*)sb)[n8 * 4 + t];
            float v0 = fmaxf(acc[g][n8][0] + bb.x, 0.f);
            float v1 = fmaxf(acc[g][n8][1] + bb.y, 0.f);
            float v2 = fmaxf(acc[g][n8][2] + bb.x, 0.f);
            float v3 = fmaxf(acc[g][n8][3] + bb.y, 0.f);
            s0 += v0 * v0 + v1 * v1;
            s1 += v2 * v2 + v3 * v3;
            acc[g][n8][0] = v0; acc[g][n8][1] = v1;
            acc[g][n8][2] = v2; acc[g][n8][3] = v3;
        }
        s0 += __shfl_xor_sync(0xffffffffu, s0, 1);
        s0 += __shfl_xor_sync(0xffffffffu, s0, 2);
        s1 += __shfl_xor_sync(0xffffffffu, s1, 1);
        s1 += __shfl_xor_sync(0xffffffffu, s1, 2);
        float n0 = fmaxf(sqrtf(s0), 1e-7f);
        float n1 = fmaxf(sqrtf(s1), 1e-7f);
        float f0 = tanhf(0.1f * n0) / (0.1f * n0);
        float f1 = tanhf(0.1f * n1) / (0.1f * n1);
        const int colA = g * 16 + q;
        const int colB = colA + 8;
#pragma unroll
        for (int n8 = 0; n8 < 4; n8++) {
            int cbase = n8 * 8 + 2 * t;
            vout[cbase * 65 + colA]       = f0 * acc[g][n8][0];
            vout[(cbase + 1) * 65 + colA] = f0 * acc[g][n8][1];
            vout[cbase * 65 + colB]       = f1 * acc[g][n8][2];
            vout[(cbase + 1) * 65 + colB] = f1 * acc[g][n8][3];
        }
    }
    __syncwarp();

    // --- coalesced stores: warp copies its row, all 32 couts ---
    {
        float* outb = out + (((size_t)b * C_OUT) << 16) + ((r0 + warp) << 8) + c0;
#pragma unroll 4
        for (int j = 0; j < 64; j++) {
            int c = j >> 1;
            int half = j & 1;
            float v = vout[c * 65 + lane + (half << 5)];
            outb[((size_t)c << 16) + lane + (half << 5)] = v;
        }
    }
}

// ---------------- launch ----------------
extern "C" void kernel_launch(void* const* d_in, const int* in_sizes, int n_in,
                              void* d_out, int out_size) {
    const float* x    = (const float*)d_in[0];
    const float* Wk   = (const float*)d_in[1];
    const float* bias = (const float*)d_in[2];
    float* out = (float*)d_out;

    cudaFuncSetAttribute(pvconv_kernel,
                         cudaFuncAttributeMaxDynamicSharedMemorySize, SMEM_BYTES);

    // kernel 1: per-pixel log0 scale
    log0_scale_kernel<<<(B_SZ * PLANE) / 256, 256>>>(x);

    // kernel 2: tf32 tensor-core conv + bias + relu + exp0
    dim3 grid(HW_DIM / TW, HW_DIM / TH, B_SZ);   // (4, 32, 4) = 512 blocks
    pvconv_kernel<<<grid, NTHREADS, SMEM_BYTES>>>(x, Wk, bias, out);
}

// round 6
// speedup vs baseline: 2.4793x; 1.3631x over previous
#include <cuda_runtime.h>

// ---------------- problem constants ----------------
#define B_SZ   4
#define C_IN   32
#define C_OUT  32
#define HW_DIM 256
#define PLANE  (HW_DIM * HW_DIM)   // 65536
#define KTAPS  9

// conv tile: 64 cols x 8 rows per block, 256 threads = 8 warps (1 row/warp)
// cin processed in 2 passes of 16 channels -> smem small enough for 2 blocks/SM
#define TW 64
#define TH 8
#define IW 66
#define IH 10
#define NTHREADS 256
#define CSPLIT 16
#define NPASS  (C_IN / CSPLIT)     // 2

#define CIN_STRIDE 664                    // 660 padded to 664
#define SU_FLOATS (CSPLIT * CIN_STRIDE)   // 10624 (one cin pass)
#define SWF_FLOATS (36 * 4 * 64)          // 9216: [kstep][n8][lane][reg] B fragments
#define SS_FLOATS (IH * IW)               // 660
#define SB_FLOATS 32
#define SMEM_FLOATS (SU_FLOATS + SWF_FLOATS + SS_FLOATS + SB_FLOATS)
#define SMEM_BYTES  (SMEM_FLOATS * 4)     // ~82.1 KB -> 2 blocks/SM
// epilogue staging overlays su+swf: needs 8*32*65 = 16640 floats <= 19840 ok

// scratch for log0 scale factors (static __device__: no allocations allowed)
__device__ float g_S[B_SZ * PLANE];

// ---------------- helpers ----------------
__device__ __forceinline__ unsigned to_tf32(float x) {
    unsigned r;
    asm("cvt.rna.tf32.f32 %0, %1;" : "=r"(r) : "f"(x));
    return r;
}

__device__ __forceinline__ void mma_tf32(float* c,
                                         unsigned a0, unsigned a1,
                                         unsigned a2, unsigned a3,
                                         unsigned b0, unsigned b1) {
    asm("mma.sync.aligned.m16n8k8.row.col.f32.tf32.tf32.f32 "
        "{%0,%1,%2,%3},{%4,%5,%6,%7},{%8,%9},{%0,%1,%2,%3};"
        : "+f"(c[0]), "+f"(c[1]), "+f"(c[2]), "+f"(c[3])
        : "r"(a0), "r"(a1), "r"(a2), "r"(a3), "r"(b0), "r"(b1));
}

// ---------------- kernel 1: log0 scale per pixel ----------------
__global__ void log0_scale_kernel(const float* __restrict__ x) {
    int pid = blockIdx.x * blockDim.x + threadIdx.x;   // 0 .. B*PLANE-1
    int b = pid >> 16;
    int p = pid & (PLANE - 1);
    const float* xb = x + ((size_t)b * C_IN) * PLANE + p;
    float ss = 0.f;
#pragma unroll
    for (int c = 0; c < C_IN; c++) {
        float v = xb[(size_t)c * PLANE];
        ss += v * v;
    }
    float n = fmaxf(sqrtf(ss), 1e-7f);
    float a = fminf(0.1f * n, 1.0f - 1e-6f);
    g_S[pid] = atanhf(a) / (0.1f * n);
}

// ---------------- kernel 2: tf32 mma implicit-GEMM conv + bias + relu + exp0 ----
__global__ __launch_bounds__(NTHREADS, 2)
void pvconv_kernel(const float* __restrict__ x,
                   const float* __restrict__ Wk,
                   const float* __restrict__ bias,
                   float* __restrict__ out) {
    extern __shared__ float sm[];
    float* su  = sm;                       // [16][CIN_STRIDE] tf32 u tile (per pass)
    float* swf = su + SU_FLOATS;           // B fragments [ks][n8][lane][2]
    float* ssc = swf + SWF_FLOATS;         // [IH][IW] log0 scales
    float* sb  = ssc + SS_FLOATS;          // [32] bias

    const int tid = threadIdx.x;
    const int b  = blockIdx.z;
    const int r0 = blockIdx.y * TH;
    const int c0 = blockIdx.x * TW;
    const int lane = tid & 31;
    const int warp = tid >> 5;             // = output row within tile (0..7)

    // --- stage B fragments (tf32), bias, scale tile ---
    for (int fidx = tid; fidx < SWF_FLOATS; fidx += NTHREADS) {
        int reg  = fidx & 1;
        int pair = fidx >> 1;
        int ls   = pair & 31;
        int n8ks = pair >> 5;
        int n8   = n8ks & 3;
        int ks   = n8ks >> 2;
        int tap  = ks >> 2;
        int cc4  = ks & 3;
        int cin  = cc4 * 8 + (ls & 3) + 4 * reg;   // B row (k)
        int cout = n8 * 8 + (ls >> 2);             // B col (n)
        float v = Wk[tap * 1024 + cout * 32 + cin];
        swf[fidx] = __uint_as_float(to_tf32(v));
    }
    if (tid < 32) sb[tid] = bias[tid];
    {
        const float* Sb = g_S + ((size_t)b << 16);
        for (int idx = tid; idx < SS_FLOATS; idx += NTHREADS) {
            int rr = idx / IW;
            int cc = idx - rr * IW;
            int gh = r0 - 1 + rr, gw = c0 - 1 + cc;
            float v = 0.f;
            if ((unsigned)gh < (unsigned)HW_DIM && (unsigned)gw < (unsigned)HW_DIM)
                v = Sb[(gh << 8) + gw];
            ssc[idx] = v;
        }
    }

    float acc[4][4][4];                    // [g16][n8][reg]
#pragma unroll
    for (int g = 0; g < 4; g++)
#pragma unroll
        for (int n = 0; n < 4; n++)
#pragma unroll
            for (int r = 0; r < 4; r++) acc[g][n][r] = 0.f;

    const int q = lane >> 2;               // 0..7: pixel-col-within-m16
    const int t = lane & 3;                // 0..3: cin-within-chunk / cout pair
    const float* xb = x + (((size_t)b * C_IN) << 16);

#pragma unroll 1
    for (int pass = 0; pass < NPASS; pass++) {
        __syncthreads();   // phase-1 done / previous pass mma done
        // --- stage scaled u tile (this cin pass) as tf32 ---
        for (int idx = tid; idx < CSPLIT * (IH * IW); idx += NTHREADS) {
            int cin = idx / (IH * IW);
            int rem = idx - cin * (IH * IW);
            int rr = rem / IW;
            int cc = rem - rr * IW;
            int gh = r0 - 1 + rr, gw = c0 - 1 + cc;
            float v = 0.f;
            if ((unsigned)gh < (unsigned)HW_DIM && (unsigned)gw < (unsigned)HW_DIM)
                v = xb[((size_t)(pass * CSPLIT + cin) << 16) + (gh << 8) + gw] * ssc[rem];
            su[cin * CIN_STRIDE + rem] = __uint_as_float(to_tf32(v));
        }
        __syncthreads();

        // --- mma: 9 taps x 2 cin-chunks of 8 ---
#pragma unroll 1
        for (int tap = 0; tap < KTAPS; tap++) {
            const int ki = tap / 3;
            const int kj = tap - ki * 3;
            const float* urow = su + (warp + ki) * IW + q + kj;
#pragma unroll
            for (int cc2 = 0; cc2 < 2; cc2++) {
                const float* ap = urow + (cc2 * 8 + t) * CIN_STRIDE;
                unsigned a[4][4];
#pragma unroll
                for (int g = 0; g < 4; g++) {
                    a[g][0] = __float_as_uint(ap[g * 16]);
                    a[g][1] = __float_as_uint(ap[g * 16 + 8]);
                    a[g][2] = __float_as_uint(ap[g * 16 + 4 * CIN_STRIDE]);
                    a[g][3] = __float_as_uint(ap[g * 16 + 8 + 4 * CIN_STRIDE]);
                }
                const float2* bbase =
                    (const float2*)swf + (size_t)(tap * 4 + pass * 2 + cc2) * 128 + lane;
#pragma unroll
                for (int n8 = 0; n8 < 4; n8++) {
                    float2 bb = bbase[n8 * 32];
                    unsigned b0 = __float_as_uint(bb.x);
                    unsigned b1 = __float_as_uint(bb.y);
#pragma unroll
                    for (int g = 0; g < 4; g++)
                        mma_tf32(acc[g][n8], a[g][0], a[g][1], a[g][2], a[g][3], b0, b1);
                }
            }
        }
    }

    __syncthreads();    // all mma done -> safe to reuse su+swf as vout staging

    // --- epilogue: bias + relu + exp0 (4-lane butterfly for the cout norm) ---
    float* vout = sm + warp * (C_OUT * 65);   // [cout][65] per-warp staging
#pragma unroll
    for (int g = 0; g < 4; g++) {
        float s0 = 0.f, s1 = 0.f;
#pragma unroll
        for (int n8 = 0; n8 < 4; n8++) {
            float2 bb = ((const float2*)sb)[n8 * 4 + t];
            float v0 = fmaxf(acc[g][n8][0] + bb.x, 0.f);
            float v1 = fmaxf(acc[g][n8][1] + bb.y, 0.f);
            float v2 = fmaxf(acc[g][n8][2] + bb.x, 0.f);
            float v3 = fmaxf(acc[g][n8][3] + bb.y, 0.f);
            s0 += v0 * v0 + v1 * v1;
            s1 += v2 * v2 + v3 * v3;
            acc[g][n8][0] = v0; acc[g][n8][1] = v1;
            acc[g][n8][2] = v2; acc[g][n8][3] = v3;
        }
        s0 += __shfl_xor_sync(0xffffffffu, s0, 1);
        s0 += __shfl_xor_sync(0xffffffffu, s0, 2);
        s1 += __shfl_xor_sync(0xffffffffu, s1, 1);
        s1 += __shfl_xor_sync(0xffffffffu, s1, 2);
        float n0 = fmaxf(sqrtf(s0), 1e-7f);
        float n1 = fmaxf(sqrtf(s1), 1e-7f);
        float f0 = tanhf(0.1f * n0) / (0.1f * n0);
        float f1 = tanhf(0.1f * n1) / (0.1f * n1);
        const int colA = g * 16 + q;
        const int colB = colA + 8;
#pragma unroll
        for (int n8 = 0; n8 < 4; n8++) {
            int cbase = n8 * 8 + 2 * t;
            vout[cbase * 65 + colA]       = f0 * acc[g][n8][0];
            vout[(cbase + 1) * 65 + colA] = f0 * acc[g][n8][1];
            vout[cbase * 65 + colB]       = f1 * acc[g][n8][2];
            vout[(cbase + 1) * 65 + colB] = f1 * acc[g][n8][3];
        }
    }
    __syncwarp();

    // --- coalesced stores: warp copies its row, all 32 couts ---
    {
        float* outb = out + (((size_t)b * C_OUT) << 16) + ((r0 + warp) << 8) + c0;
#pragma unroll 4
        for (int j = 0; j < 64; j++) {
            int c = j >> 1;
            int half = j & 1;
            float v = vout[c * 65 + lane + (half << 5)];
            outb[((size_t)c << 16) + lane + (half << 5)] = v;
        }
    }
}

// ---------------- launch ----------------
extern "C" void kernel_launch(void* const* d_in, const int* in_sizes, int n_in,
                              void* d_out, int out_size) {
    const float* x    = (const float*)d_in[0];
    const float* Wk   = (const float*)d_in[1];
    const float* bias = (const float*)d_in[2];
    float* out = (float*)d_out;

    cudaFuncSetAttribute(pvconv_kernel,
                         cudaFuncAttributeMaxDynamicSharedMemorySize, SMEM_BYTES);

    // kernel 1: per-pixel log0 scale
    log0_scale_kernel<<<(B_SZ * PLANE) / 256, 256>>>(x);

    // kernel 2: tf32 tensor-core conv + bias + relu + exp0
    dim3 grid(HW_DIM / TW, HW_DIM / TH, B_SZ);   // (4, 32, 4) = 512 blocks
    pvconv_kernel<<<grid, NTHREADS, SMEM_BYTES>>>(x, Wk, bias, out);
}

// round 7
// speedup vs baseline: 2.8571x; 1.1524x over previous
#include <cuda_runtime.h>

// ---------------- problem constants ----------------
#define B_SZ   4
#define C_IN   32
#define C_OUT  32
#define HW_DIM 256
#define PLANE  (HW_DIM * HW_DIM)   // 65536
#define KTAPS  9

// conv tile: 64 cols x 8 rows per block, 256 threads = 8 warps (1 row/warp)
// cin processed in 4 passes of 8 channels (one k8 chunk per tap per pass)
#define TW 64
#define TH 8
#define IW 66
#define IH 10
#define POS (IH * IW)              // 660 halo positions
#define NTHREADS 256
#define CSPLIT 8
#define NPASS  (C_IN / CSPLIT)     // 4
#define PPAD 10                    // floats per position (8 cin + 2 pad)

#define SU_FLOATS (POS * PPAD)            // 6600
#define SWF_FLOATS (36 * 4 * 64)          // 9216: [kstep][n8][lane][reg] B frags
#define SS_FLOATS POS                     // 660
#define SB_FLOATS 32
// epilogue vout overlay needs 8 warps * 32*65 = 16640 floats (> sum above)
#define SMEM_FLOATS 16640
#define SMEM_BYTES  (SMEM_FLOATS * 4)     // 66560 B -> 2 blocks/SM

// scratch for log0 scale factors (static __device__: no allocations allowed)
__device__ float g_S[B_SZ * PLANE];

// ---------------- helpers ----------------
__device__ __forceinline__ unsigned to_tf32(float x) {
    unsigned r;
    asm("cvt.rna.tf32.f32 %0, %1;" : "=r"(r) : "f"(x));
    return r;
}

__device__ __forceinline__ void mma_tf32(float* c,
                                         unsigned a0, unsigned a1,
                                         unsigned a2, unsigned a3,
                                         unsigned b0, unsigned b1) {
    asm("mma.sync.aligned.m16n8k8.row.col.f32.tf32.tf32.f32 "
        "{%0,%1,%2,%3},{%4,%5,%6,%7},{%8,%9},{%0,%1,%2,%3};"
        : "+f"(c[0]), "+f"(c[1]), "+f"(c[2]), "+f"(c[3])
        : "r"(a0), "r"(a1), "r"(a2), "r"(a3), "r"(b0), "r"(b1));
}

// ---------------- kernel 1: log0 scale per pixel ----------------
__global__ void log0_scale_kernel(const float* __restrict__ x) {
    int pid = blockIdx.x * blockDim.x + threadIdx.x;   // 0 .. B*PLANE-1
    int b = pid >> 16;
    int p = pid & (PLANE - 1);
    const float* xb = x + ((size_t)b * C_IN) * PLANE + p;
    float ss = 0.f;
#pragma unroll
    for (int c = 0; c < C_IN; c++) {
        float v = xb[(size_t)c * PLANE];
        ss += v * v;
    }
    float n = fmaxf(sqrtf(ss), 1e-7f);
    float a = fminf(0.1f * n, 1.0f - 1e-6f);
    g_S[pid] = atanhf(a) / (0.1f * n);
}

// ---------------- kernel 2: tf32 mma implicit-GEMM conv + bias + relu + exp0 ----
// u-tile layout: su[pos*10 + slot(c)], slot(c) = 2*(c&3) + (c>>2)  (c = local cin)
// -> A fragment pair (k=t, k=t+4) is one LDS.64 at float2 index pos*5 + t.
__global__ __launch_bounds__(NTHREADS, 2)
void pvconv_kernel(const float* __restrict__ x,
                   const float* __restrict__ Wk,
                   const float* __restrict__ bias,
                   float* __restrict__ out) {
    extern __shared__ float sm[];
    float* su  = sm;                       // [POS][PPAD] permuted u tile (per pass)
    float* swf = su + SU_FLOATS;           // B fragments [ks][n8][lane][2]
    float* ssc = swf + SWF_FLOATS;         // [POS] log0 scales
    float* sb  = ssc + SS_FLOATS;          // [32] bias

    const int tid = threadIdx.x;
    const int b  = blockIdx.z;
    const int r0 = blockIdx.y * TH;
    const int c0 = blockIdx.x * TW;
    const int lane = tid & 31;
    const int warp = tid >> 5;             // output row within tile (0..7)

    // --- stage B fragments (tf32), bias, scale tile ---
    for (int fidx = tid; fidx < SWF_FLOATS; fidx += NTHREADS) {
        int reg  = fidx & 1;
        int pair = fidx >> 1;
        int ls   = pair & 31;
        int n8ks = pair >> 5;
        int n8   = n8ks & 3;
        int ks   = n8ks >> 2;
        int tap  = ks >> 2;
        int cc4  = ks & 3;                         // = pass index
        int cin  = cc4 * 8 + (ls & 3) + 4 * reg;   // B row (k)
        int cout = n8 * 8 + (ls >> 2);             // B col (n)
        float v = Wk[tap * 1024 + cout * 32 + cin];
        swf[fidx] = __uint_as_float(to_tf32(v));
    }
    if (tid < 32) sb[tid] = bias[tid];
    {
        const float* Sb = g_S + ((size_t)b << 16);
        for (int idx = tid; idx < SS_FLOATS; idx += NTHREADS) {
            int rr = idx / IW;
            int cc = idx - rr * IW;
            int gh = r0 - 1 + rr, gw = c0 - 1 + cc;
            float v = 0.f;
            if ((unsigned)gh < (unsigned)HW_DIM && (unsigned)gw < (unsigned)HW_DIM)
                v = Sb[(gh << 8) + gw];
            ssc[idx] = v;
        }
    }
    __syncthreads();

    // --- precompute this thread's halo positions (<=3) once ---
    int   s_base[3];   // su write base (float index)
    int   s_xoff[3];   // x plane offset (or 0 if out of bounds)
    float s_val[3];    // log0 scale (0 if out of bounds)
    int   myN = 0;
#pragma unroll
    for (int i = 0; i < 3; i++) {
        int p = tid + i * NTHREADS;
        if (p < POS) {
            int rr = p / IW;
            int cc = p - rr * IW;
            int gh = r0 - 1 + rr, gw = c0 - 1 + cc;
            bool ok = (unsigned)gh < (unsigned)HW_DIM && (unsigned)gw < (unsigned)HW_DIM;
            s_base[i] = p * PPAD;
            s_xoff[i] = ok ? ((gh << 8) + gw) : 0;
            s_val[i]  = ok ? ssc[p] : 0.f;
            myN = i + 1;
        }
    }

    float acc[4][4][4];                    // [g16][n8][reg]
#pragma unroll
    for (int g = 0; g < 4; g++)
#pragma unroll
        for (int n = 0; n < 4; n++)
#pragma unroll
            for (int r = 0; r < 4; r++) acc[g][n][r] = 0.f;

    const int q = lane >> 2;               // 0..7: pixel-col-within-m16 / B cout
    const int t = lane & 3;                // 0..3: k-within-chunk
    const float* xb = x + (((size_t)b * C_IN) << 16);

#pragma unroll 1
    for (int pass = 0; pass < NPASS; pass++) {
        if (pass) __syncthreads();         // previous mma done reading su
        // --- stage scaled u tile (8 cins), permuted slots, tf32 ---
        const float* gp0 = xb + ((size_t)(pass * CSPLIT) << 16);
#pragma unroll
        for (int i = 0; i < 3; i++) {
            if (i < myN) {
                const float* gp = gp0 + s_xoff[i];
                float* sp = su + s_base[i];
                float sv = s_val[i];
#pragma unroll
                for (int c = 0; c < CSPLIT; c++) {
                    float v = gp[(size_t)c << 16] * sv;   // sv==0 handles OOB
                    sp[2 * (c & 3) + (c >> 2)] = __uint_as_float(to_tf32(v));
                }
            }
        }
        __syncthreads();

        // --- mma: 9 taps, one k8 chunk each ---
#pragma unroll 1
        for (int tap = 0; tap < KTAPS; tap++) {
            const int ki = tap / 3;
            const int kj = tap - ki * 3;
            // B prefetch (4 x LDS.64)
            const float2* bbase =
                (const float2*)swf + (size_t)(tap * 4 + pass) * 128 + lane;
            float2 bfr[4];
#pragma unroll
            for (int n8 = 0; n8 < 4; n8++) bfr[n8] = bbase[n8 * 32];

            // A fragments: 8 x LDS.64
            const float2* ap =
                (const float2*)su + ((warp + ki) * IW + q + kj) * (PPAD / 2) + t;
            unsigned a[4][4];
#pragma unroll
            for (int g = 0; g < 4; g++) {
                float2 lo = ap[g * 16 * (PPAD / 2)];            // row g*16+q
                float2 hi = ap[(g * 16 + 8) * (PPAD / 2)];      // row g*16+q+8
                a[g][0] = __float_as_uint(lo.x);   // k=t
                a[g][2] = __float_as_uint(lo.y);   // k=t+4
                a[g][1] = __float_as_uint(hi.x);
                a[g][3] = __float_as_uint(hi.y);
            }
#pragma unroll
            for (int n8 = 0; n8 < 4; n8++) {
                unsigned b0 = __float_as_uint(bfr[n8].x);
                unsigned b1 = __float_as_uint(bfr[n8].y);
#pragma unroll
                for (int g = 0; g < 4; g++)
                    mma_tf32(acc[g][n8], a[g][0], a[g][1], a[g][2], a[g][3], b0, b1);
            }
        }
    }

    // preload bias pairs to regs (vout overlay will clobber sb)
    float2 bfrag[4];
#pragma unroll
    for (int n8 = 0; n8 < 4; n8++) bfrag[n8] = ((const float2*)sb)[n8 * 4 + t];

    __syncthreads();    // all mma done -> reuse smem as vout staging

    // --- epilogue: bias + relu + exp0 (4-lane butterfly for the cout norm) ---
    float* vout = sm + warp * (C_OUT * 65);   // [cout][65] per-warp staging
#pragma unroll
    for (int g = 0; g < 4; g++) {
        float s0 = 0.f, s1 = 0.f;
#pragma unroll
        for (int n8 = 0; n8 < 4; n8++) {
            float2 bb = bfrag[n8];
            float v0 = fmaxf(acc[g][n8][0] + bb.x, 0.f);
            float v1 = fmaxf(acc[g][n8][1] + bb.y, 0.f);
            float v2 = fmaxf(acc[g][n8][2] + bb.x, 0.f);
            float v3 = fmaxf(acc[g][n8][3] + bb.y, 0.f);
            s0 += v0 * v0 + v1 * v1;
            s1 += v2 * v2 + v3 * v3;
            acc[g][n8][0] = v0; acc[g][n8][1] = v1;
            acc[g][n8][2] = v2; acc[g][n8][3] = v3;
        }
        s0 += __shfl_xor_sync(0xffffffffu, s0, 1);
        s0 += __shfl_xor_sync(0xffffffffu, s0, 2);
        s1 += __shfl_xor_sync(0xffffffffu, s1, 1);
        s1 += __shfl_xor_sync(0xffffffffu, s1, 2);
        float n0 = fmaxf(sqrtf(s0), 1e-7f);
        float n1 = fmaxf(sqrtf(s1), 1e-7f);
        float f0 = tanhf(0.1f * n0) / (0.1f * n0);
        float f1 = tanhf(0.1f * n1) / (0.1f * n1);
        const int colA = g * 16 + q;
        const int colB = colA + 8;
#pragma unroll
        for (int n8 = 0; n8 < 4; n8++) {
            int cbase = n8 * 8 + 2 * t;
            vout[cbase * 65 + colA]       = f0 * acc[g][n8][0];
            vout[(cbase + 1) * 65 + colA] = f0 * acc[g][n8][1];
            vout[cbase * 65 + colB]       = f1 * acc[g][n8][2];
            vout[(cbase + 1) * 65 + colB] = f1 * acc[g][n8][3];
        }
    }
    __syncwarp();

    // --- coalesced stores: warp copies its row, all 32 couts ---
    {
        float* outb = out + (((size_t)b * C_OUT) << 16) + ((r0 + warp) << 8) + c0;
#pragma unroll 4
        for (int j = 0; j < 64; j++) {
            int c = j >> 1;
            int half = j & 1;
            float v = vout[c * 65 + lane + (half << 5)];
            outb[((size_t)c << 16) + lane + (half << 5)] = v;
        }
    }
}

// ---------------- launch ----------------
extern "C" void kernel_launch(void* const* d_in, const int* in_sizes, int n_in,
                              void* d_out, int out_size) {
    const float* x    = (const float*)d_in[0];
    const float* Wk   = (const float*)d_in[1];
    const float* bias = (const float*)d_in[2];
    float* out = (float*)d_out;

    cudaFuncSetAttribute(pvconv_kernel,
                         cudaFuncAttributeMaxDynamicSharedMemorySize, SMEM_BYTES);

    // kernel 1: per-pixel log0 scale
    log0_scale_kernel<<<(B_SZ * PLANE) / 256, 256>>>(x);

    // kernel 2: tf32 tensor-core conv + bias + relu + exp0
    dim3 grid(HW_DIM / TW, HW_DIM / TH, B_SZ);   // (4, 32, 4) = 512 blocks
    pvconv_kernel<<<grid, NTHREADS, SMEM_BYTES>>>(x, Wk, bias, out);
}